// round 10
// baseline (speedup 1.0000x reference)
#include <cuda_runtime.h>
#include <cuda_bf16.h>
#include <cstdint>

// ============================================================================
// VQMetaBaseline via mma.sync bf16 (compute_103-safe):
// z_e = X @ W + b with truncation-based bf16 hi/lo split, 3 exact-product
// passes (hi*hi + hi*lo + lo*hi) as grid-z phases, fp32 accumulate ->
// argmin-index parity with fp32 reference. Tail: fused reduce+nearest,
// transposed-codebook proto/logits with shfl block reductions.
// ============================================================================

#define IN_DIM 49152
#define NDIM   512
#define NK     512
#define MROWS  400
#define MPAD   512
#define NSHOT  100

// GEMM tiling (R3/R7-proven config)
#define BM 128
#define BN 128
#define BK 32
#define STAGES 4
#define STG_BYTES 16384            // A 8KB + B 8KB per stage
#define SMEM_GEMM (STAGES * STG_BYTES)   // 64 KB -> 2 CTAs/SM

// split-K: 3 phases (hihi, hilo, lohi) x 6 sub-splits
#define SUBSPLITS 6
#define TOTSPLITS 18
#define KSPLIT (IN_DIM / SUBSPLITS)      // 8192
#define NT (KSPLIT / BK)                 // 256 k-tiles per CTA

// conv_all work partition
#define A_BLOCKS ((int)((size_t)MPAD * IN_DIM / (256 * 16)))  // 6144
#define B_KT     (IN_DIM / 64)                                // 768
#define B_BLOCKS (B_KT * (NDIM / 64))                         // 6144
#define CBT_BLOCKS 64                                         // 8x8 64x64 tiles
#define CONV_GRID (A_BLOCKS + B_BLOCKS + CBT_BLOCKS + 1)

// ---- scratch (static device globals; no runtime allocation) ----------------
__device__ __align__(128) __nv_bfloat16 gAhi[(size_t)MPAD * IN_DIM];
__device__ __align__(128) __nv_bfloat16 gAlo[(size_t)MPAD * IN_DIM];
__device__ __align__(128) __nv_bfloat16 gBhi[(size_t)NDIM * IN_DIM];
__device__ __align__(128) __nv_bfloat16 gBlo[(size_t)NDIM * IN_DIM];
__device__ float g_part[(size_t)TOTSPLITS * MPAD * NDIM];
__device__ float g_cbT[NK * NDIM];      // codebook transposed [K][D]
__device__ float g_cnorm[NK];           // 0.5 * ||c_k||^2
__device__ int   g_idx[MROWS];
__device__ float g_proto[20 * NDIM];

// ---- helpers ----------------------------------------------------------------
__device__ __forceinline__ uint32_t smem_u32(const void* p) {
    uint32_t a;
    asm("{ .reg .u64 t; cvta.to.shared.u64 t, %1; cvt.u32.u64 %0, t; }"
        : "=r"(a) : "l"(p));
    return a;
}
__device__ __forceinline__ void cp16(uint32_t dst, const void* src) {
    asm volatile("cp.async.cg.shared.global [%0], [%1], 16;"
                 :: "r"(dst), "l"(src) : "memory");
}
#define CP_COMMIT() asm volatile("cp.async.commit_group;" ::: "memory")
#define CP_WAIT2()  asm volatile("cp.async.wait_group 2;" ::: "memory")

__device__ __forceinline__ void ldsm4(uint32_t& r0, uint32_t& r1,
                                      uint32_t& r2, uint32_t& r3, uint32_t a) {
    asm volatile("ldmatrix.sync.aligned.m8n8.x4.shared.b16 {%0,%1,%2,%3}, [%4];"
                 : "=r"(r0), "=r"(r1), "=r"(r2), "=r"(r3) : "r"(a));
}
__device__ __forceinline__ void mma16816(float* c, const uint32_t* a,
                                         const uint32_t* b) {
    asm volatile(
        "mma.sync.aligned.m16n8k16.row.col.f32.bf16.bf16.f32 "
        "{%0,%1,%2,%3},{%4,%5,%6,%7},{%8,%9},{%0,%1,%2,%3};"
        : "+f"(c[0]), "+f"(c[1]), "+f"(c[2]), "+f"(c[3])
        : "r"(a[0]), "r"(a[1]), "r"(a[2]), "r"(a[3]), "r"(b[0]), "r"(b[1]));
}
__device__ __forceinline__ uint32_t toff(int r, int c) {
    return (uint32_t)(r * 64 + ((c ^ ((r >> 1) & 3)) << 4));
}

// ---- fast truncation split ---------------------------------------------------
__device__ __forceinline__ void split2(float f0, float f1,
                                       uint32_t& hp, uint32_t& lp) {
    const uint32_t u0 = __float_as_uint(f0);
    const uint32_t u1 = __float_as_uint(f1);
    asm("prmt.b32 %0, %1, %2, 0x7632;" : "=r"(hp) : "r"(u0), "r"(u1));
    const float lo0 = f0 - __uint_as_float(u0 & 0xFFFF0000u);
    const float lo1 = f1 - __uint_as_float(u1 & 0xFFFF0000u);
    asm("cvt.rn.bf16x2.f32 %0, %1, %2;" : "=r"(lp) : "f"(lo1), "f"(lo0));
}
__device__ __forceinline__ void split8(const float* f, uint4& hv, uint4& lv) {
    split2(f[0], f[1], hv.x, lv.x);
    split2(f[2], f[3], hv.y, lv.y);
    split2(f[4], f[5], hv.z, lv.z);
    split2(f[6], f[7], hv.w, lv.w);
}

// ---- block-wide sum over 512 threads (3 barriers, deterministic) ------------
__device__ __forceinline__ float blk_sum512(float v, float* s16, int t) {
    __syncthreads();                       // protect s16 reuse
    const int lane = t & 31, warp = t >> 5;
#pragma unroll
    for (int o = 16; o > 0; o >>= 1) v += __shfl_xor_sync(0xffffffffu, v, o);
    if (lane == 0) s16[warp] = v;
    __syncthreads();
    if (warp == 0) {
        float w = (lane < 16) ? s16[lane] : 0.f;
#pragma unroll
        for (int o = 8; o > 0; o >>= 1) w += __shfl_xor_sync(0xffffffffu, w, o);
        if (lane == 0) s16[0] = w;
    }
    __syncthreads();
    return s16[0];
}

// ============================================================================
// conv_all: A split | B transpose+split | cbT transpose | codebook norms
// ============================================================================
__global__ __launch_bounds__(256) void conv_all(const float* __restrict__ xs,
                                                const float* __restrict__ xq,
                                                const float* __restrict__ W,
                                                const float* __restrict__ cb) {
    __shared__ float ts[64][65];
    const int t = threadIdx.x;
    int bid = blockIdx.x;

    if (bid < A_BLOCKS) {
        const size_t e = ((size_t)bid * 256 + t) * 16;
        const int row = (int)(e / IN_DIM);
        const int col = (int)(e % IN_DIM);
        float f[16];
        const float* src = 0;
        if (row < NSHOT)      src = xs + (size_t)row * IN_DIM + col;
        else if (row < MROWS) src = xq + (size_t)(row - NSHOT) * IN_DIM + col;
        if (src) {
#pragma unroll
            for (int i = 0; i < 4; i++)
                *(float4*)&f[i * 4] = *(const float4*)(src + i * 4);
        } else {
#pragma unroll
            for (int i = 0; i < 16; i++) f[i] = 0.f;
        }
        uint4 hv0, lv0, hv1, lv1;
        split8(f,     hv0, lv0);
        split8(f + 8, hv1, lv1);
        *(uint4*)&gAhi[e]     = hv0;
        *(uint4*)&gAhi[e + 8] = hv1;
        *(uint4*)&gAlo[e]     = lv0;
        *(uint4*)&gAlo[e + 8] = lv1;
        return;
    }
    bid -= A_BLOCKS;

    if (bid < B_BLOCKS) {
        // ---- B transpose + split: 64x64 fp32 tile of enc_w
        const int k0 = (bid % B_KT) * 64;
        const int n0 = (bid / B_KT) * 64;
#pragma unroll
        for (int i = 0; i < 4; i++) {
            const int r = i * 16 + (t >> 4);
            const int c = (t & 15) * 4;
            const float4 v = *(const float4*)(W + (size_t)(k0 + r) * NDIM + n0 + c);
            ts[r][c] = v.x; ts[r][c+1] = v.y; ts[r][c+2] = v.z; ts[r][c+3] = v.w;
        }
        __syncthreads();
        const int n  = t >> 2;
        const int kc = (t & 3) * 16;
        float f[16];
#pragma unroll
        for (int j = 0; j < 16; j++) f[j] = ts[kc + j][n];
        uint4 hv0, lv0, hv1, lv1;
        split8(f,     hv0, lv0);
        split8(f + 8, hv1, lv1);
        const size_t o = (size_t)(n0 + n) * IN_DIM + k0 + kc;
        *(uint4*)&gBhi[o]     = hv0;
        *(uint4*)&gBhi[o + 8] = hv1;
        *(uint4*)&gBlo[o]     = lv0;
        *(uint4*)&gBlo[o + 8] = lv1;
        return;
    }
    bid -= B_BLOCKS;

    if (bid < CBT_BLOCKS) {
        // ---- codebook transpose: cb[D][K] -> g_cbT[K][D], 64x64 fp32 tile
        const int d0 = (bid & 7) * 64;
        const int k0 = (bid >> 3) * 64;
#pragma unroll
        for (int i = 0; i < 4; i++) {
            const int r = i * 16 + (t >> 4);
            const int c = (t & 15) * 4;
            const float4 v = *(const float4*)(cb + (size_t)(d0 + r) * NK + k0 + c);
            ts[r][c] = v.x; ts[r][c+1] = v.y; ts[r][c+2] = v.z; ts[r][c+3] = v.w;
        }
        __syncthreads();
        const int k  = t >> 2;          // local k row 0..63
        const int dc = (t & 3) * 16;    // local d chunk
#pragma unroll
        for (int j = 0; j < 16; j += 4) {
            float4 o;
            o.x = ts[dc + j][k];     o.y = ts[dc + j + 1][k];
            o.z = ts[dc + j + 2][k]; o.w = ts[dc + j + 3][k];
            *(float4*)&g_cbT[(size_t)(k0 + k) * NDIM + d0 + dc + j] = o;
        }
        return;
    }

    // ---- codebook half-norms: thread t = code k (needs 512 threads worth;
    //      256 threads -> 2 codes each)
#pragma unroll
    for (int h = 0; h < 2; h++) {
        const int k = t + h * 256;
        float s = 0.f;
#pragma unroll 4
        for (int d = 0; d < NDIM; d++) {
            const float c = cb[(size_t)d * NK + k];
            s = fmaf(c, c, s);
        }
        g_cnorm[k] = 0.5f * s;
    }
}

// ============================================================================
// noop: launch-order shim (keeps nearest_fused at ncu's captured slot #4)
// ============================================================================
__global__ void noop_kernel() {}

// ============================================================================
// HMMA GEMM (R3/R7-proven): g_part[sp] = A_ph @ B_ph^T over k slice
// ============================================================================
__global__ __launch_bounds__(256, 2) void gemm_hmma() {
    extern __shared__ char smem[];
    const uint32_t sbase = smem_u32(smem);
    const int t = threadIdx.x;
    const int wid = t >> 5, lane = t & 31;

    const int n0 = blockIdx.x * BN;
    const int m0 = blockIdx.y * BM;
    const int sp = blockIdx.z;
    const int phase = sp / SUBSPLITS;
    const size_t ksub = (size_t)(sp % SUBSPLITS) * KSPLIT;

    const __nv_bfloat16* __restrict__ A = (phase == 2) ? gAlo : gAhi;
    const __nv_bfloat16* __restrict__ B = (phase == 1) ? gBlo : gBhi;

    const int lr = t >> 2;
    const int lc = t & 3;
    const uint32_t dA1 = toff(lr, lc),        dA2 = toff(lr + 64, lc);
    const uint32_t dB1 = toff(lr, lc) + 8192, dB2 = toff(lr + 64, lc) + 8192;
    const __nv_bfloat16* pA1 = A + (size_t)(m0 + lr) * IN_DIM + ksub + lc * 8;
    const __nv_bfloat16* pA2 = pA1 + (size_t)64 * IN_DIM;
    const __nv_bfloat16* pB1 = B + (size_t)(n0 + lr) * IN_DIM + ksub + lc * 8;
    const __nv_bfloat16* pB2 = pB1 + (size_t)64 * IN_DIM;

#define LOAD_STAGE(s, kt) do {                                        \
        const uint32_t sb_ = sbase + (s) * STG_BYTES;                  \
        const size_t ko_ = (size_t)(kt) * BK;                          \
        cp16(sb_ + dA1, pA1 + ko_); cp16(sb_ + dA2, pA2 + ko_);        \
        cp16(sb_ + dB1, pB1 + ko_); cp16(sb_ + dB2, pB2 + ko_);        \
    } while (0)

    const int wm = wid >> 1, wn = wid & 1;
    const int fr = lane & 15, fc = lane >> 4;
    uint32_t aoff[2][2], boff[4][2];
#pragma unroll
    for (int mh = 0; mh < 2; mh++)
#pragma unroll
        for (int ks = 0; ks < 2; ks++)
            aoff[mh][ks] = toff(wm * 32 + mh * 16 + fr, ks * 2 + fc);
#pragma unroll
    for (int p = 0; p < 4; p++)
#pragma unroll
        for (int ks = 0; ks < 2; ks++)
            boff[p][ks] = 8192 + toff(wn * 64 + p * 16 + fr, ks * 2 + fc);

    float c[2][8][4];
#pragma unroll
    for (int i = 0; i < 2; i++)
#pragma unroll
        for (int j = 0; j < 8; j++)
#pragma unroll
            for (int k = 0; k < 4; k++) c[i][j][k] = 0.f;

#pragma unroll
    for (int s = 0; s < STAGES - 1; s++) {
        LOAD_STAGE(s, s);
        CP_COMMIT();
    }

    for (int kt = 0; kt < NT; ++kt) {
        CP_WAIT2();
        __syncthreads();

        if (kt + STAGES - 1 < NT)
            LOAD_STAGE((kt + STAGES - 1) & (STAGES - 1), kt + STAGES - 1);
        CP_COMMIT();

        const uint32_t sb = sbase + (kt & (STAGES - 1)) * STG_BYTES;
#pragma unroll
        for (int ks = 0; ks < 2; ks++) {
            uint32_t a0[4], a1[4];
            ldsm4(a0[0], a0[1], a0[2], a0[3], sb + aoff[0][ks]);
            ldsm4(a1[0], a1[1], a1[2], a1[3], sb + aoff[1][ks]);
#pragma unroll
            for (int p = 0; p < 4; p++) {
                uint32_t r0, r1, r2, r3;
                ldsm4(r0, r1, r2, r3, sb + boff[p][ks]);
                uint32_t b0[2] = { r0, r2 };
                uint32_t b1[2] = { r1, r3 };
                mma16816(c[0][2*p],     a0, b0);
                mma16816(c[1][2*p],     a1, b0);
                mma16816(c[0][2*p + 1], a0, b1);
                mma16816(c[1][2*p + 1], a1, b1);
            }
        }
    }

    float* base = g_part + (size_t)sp * MPAD * NDIM;
    const int row0 = m0 + wm * 32 + (lane >> 2);
    const int col0 = n0 + wn * 64 + (lane & 3) * 2;
#pragma unroll
    for (int mi = 0; mi < 2; mi++)
#pragma unroll
        for (int j = 0; j < 8; j++) {
            const int r = row0 + mi * 16;
            const int cc = col0 + j * 8;
            *(float2*)&base[(size_t)r * NDIM + cc]       = make_float2(c[mi][j][0], c[mi][j][1]);
            *(float2*)&base[(size_t)(r + 8) * NDIM + cc] = make_float2(c[mi][j][2], c[mi][j][3]);
        }
}

// ============================================================================
// nearest_fused: split-K reduce + bias + nearest-codebook argmax.
// 100 blocks x 512 threads, 4 rows per block. Deterministic.
// argmax_k ( z.c_k - 0.5||c_k||^2 ), tie -> min k.
// ============================================================================
__global__ __launch_bounds__(512) void nearest_fused(const float* __restrict__ bias,
                                                     const float* __restrict__ cb) {
    __shared__ float zs[4][NDIM];
    __shared__ float sv[4][16];
    __shared__ int   si[4][16];
    const int t = threadIdx.x;
    const int lane = t & 31, warp = t >> 5;
    const int r0 = blockIdx.x * 4;

    // inline split-K reduction + bias (fixed order -> deterministic)
#pragma unroll
    for (int g = 0; g < 4; g++) {
        float s = 0.f;
#pragma unroll
        for (int p = 0; p < TOTSPLITS; p++)
            s += g_part[(size_t)p * MPAD * NDIM + (size_t)(r0 + g) * NDIM + t];
        zs[g][t] = s + bias[t];
    }
    __syncthreads();

    // dot products: thread t owns codebook column k = t (coalesced cb reads)
    float dot[4] = { 0.f, 0.f, 0.f, 0.f };
#pragma unroll 4
    for (int d = 0; d < NDIM; d++) {
        const float c = cb[(size_t)d * NK + t];
#pragma unroll
        for (int g = 0; g < 4; g++) dot[g] = fmaf(zs[g][d], c, dot[g]);
    }
    const float hn = g_cnorm[t];

    // argmax (max value, tie -> min index) per row
#pragma unroll
    for (int g = 0; g < 4; g++) {
        float v = dot[g] - hn;
        int   idx = t;
#pragma unroll
        for (int o = 16; o > 0; o >>= 1) {
            const float ov = __shfl_down_sync(0xffffffffu, v, o);
            const int   oi = __shfl_down_sync(0xffffffffu, idx, o);
            if (ov > v || (ov == v && oi < idx)) { v = ov; idx = oi; }
        }
        if (lane == 0) { sv[g][warp] = v; si[g][warp] = idx; }
    }
    __syncthreads();
    if (warp < 4) {     // warp g reduces its row's 16 partials
        const int g = warp;
        float v = (lane < 16) ? sv[g][lane] : -3.4e38f;
        int   idx = (lane < 16) ? si[g][lane] : 0x7fffffff;
#pragma unroll
        for (int o = 8; o > 0; o >>= 1) {
            const float ov = __shfl_down_sync(0xffffffffu, v, o);
            const int   oi = __shfl_down_sync(0xffffffffu, idx, o);
            if (ov > v || (ov == v && oi < idx)) { v = ov; idx = oi; }
        }
        if (lane == 0) g_idx[r0 + g] = idx;
    }
}

// ============================================================================
// prototypes: mean of 5 quantized shots (coalesced cbT gathers), L2-normalized
// ============================================================================
__global__ __launch_bounds__(512) void proto_kernel() {
    __shared__ float s16[16];
    const int bw = blockIdx.x, t = threadIdx.x;
    float p = 0.f;
#pragma unroll
    for (int s = 0; s < 5; s++)
        p += g_cbT[(size_t)g_idx[bw * 5 + s] * NDIM + t];
    p *= 0.2f;
    const float nrm = blk_sum512(p * p, s16, t);
    g_proto[bw * NDIM + t] = p * rsqrtf(nrm);
}

// ============================================================================
// logits: coalesced cbT query gather, shfl block reductions
// ============================================================================
__global__ __launch_bounds__(512) void logits_kernel(
    const float* __restrict__ tptr, float* __restrict__ out) {
    __shared__ float s16[16];
    const int bq = blockIdx.x, t = threadIdx.x;
    const int b = bq / 75;
    const float v = g_cbT[(size_t)g_idx[NSHOT + bq] * NDIM + t];
    const float nrm = blk_sum512(v * v, s16, t);
    const float vn = v * rsqrtf(nrm);
    const float temp = *tptr;
#pragma unroll
    for (int w = 0; w < 5; w++) {
        const float d = blk_sum512(vn * g_proto[(b * 5 + w) * NDIM + t], s16, t);
        if (t == 0) out[bq * 5 + w] = d * temp;
    }
}

// ============================================================================
extern "C" void kernel_launch(void* const* d_in, const int* in_sizes, int n_in,
                              void* d_out, int out_size) {
    const float* xs   = (const float*)d_in[0];
    const float* xq   = (const float*)d_in[1];
    const float* W    = (const float*)d_in[2];
    const float* bias = (const float*)d_in[3];
    const float* cb   = (const float*)d_in[4];
    const float* temp = (const float*)d_in[5];
    float* out = (float*)d_out;

    cudaFuncSetAttribute(gemm_hmma, cudaFuncAttributeMaxDynamicSharedMemorySize,
                         SMEM_GEMM);

    conv_all<<<CONV_GRID, 256>>>(xs, xq, W, cb);
    gemm_hmma<<<dim3(NDIM / BN, MPAD / BM, TOTSPLITS), 256, SMEM_GEMM>>>();
    noop_kernel<<<1, 32>>>();   // shim: nearest_fused lands at ncu slot #4
    nearest_fused<<<MROWS / 4, 512>>>(bias, cb);
    proto_kernel<<<20, 512>>>();
    logits_kernel<<<300, 512>>>(temp, out);
}

// round 11
// speedup vs baseline: 1.3564x; 1.3564x over previous
#include <cuda_runtime.h>
#include <cuda_bf16.h>
#include <cstdint>

// ============================================================================
// VQMetaBaseline via mma.sync bf16 (compute_103-safe):
// z_e = X @ W + b with truncation-based bf16 hi/lo split, 3 exact-product
// passes (hi*hi + hi*lo + lo*hi) as grid-z phases, fp32 accumulate ->
// argmin-index parity with fp32 reference. Tail: warp-per-code norms,
// 400-block fused reduce+nearest, transposed-codebook proto/logits.
// ============================================================================

#define IN_DIM 49152
#define NDIM   512
#define NK     512
#define MROWS  400
#define MPAD   512
#define NSHOT  100

// GEMM tiling (R3/R7-proven config)
#define BM 128
#define BN 128
#define BK 32
#define STAGES 4
#define STG_BYTES 16384            // A 8KB + B 8KB per stage
#define SMEM_GEMM (STAGES * STG_BYTES)   // 64 KB -> 2 CTAs/SM

// split-K: 3 phases (hihi, hilo, lohi) x 6 sub-splits
#define SUBSPLITS 6
#define TOTSPLITS 18
#define KSPLIT (IN_DIM / SUBSPLITS)      // 8192
#define NT (KSPLIT / BK)                 // 256 k-tiles per CTA

// conv_all work partition
#define A_BLOCKS ((int)((size_t)MPAD * IN_DIM / (256 * 16)))  // 6144
#define B_KT     (IN_DIM / 64)                                // 768
#define B_BLOCKS (B_KT * (NDIM / 64))                         // 6144
#define CBT_BLOCKS 64                                         // 8x8 64x64 tiles
#define CONV_GRID (A_BLOCKS + B_BLOCKS + CBT_BLOCKS)

// ---- scratch (static device globals; no runtime allocation) ----------------
__device__ __align__(128) __nv_bfloat16 gAhi[(size_t)MPAD * IN_DIM];
__device__ __align__(128) __nv_bfloat16 gAlo[(size_t)MPAD * IN_DIM];
__device__ __align__(128) __nv_bfloat16 gBhi[(size_t)NDIM * IN_DIM];
__device__ __align__(128) __nv_bfloat16 gBlo[(size_t)NDIM * IN_DIM];
__device__ float g_part[(size_t)TOTSPLITS * MPAD * NDIM];
__device__ float g_cbT[NK * NDIM];      // codebook transposed [K][D]
__device__ float g_cnorm[NK];           // 0.5 * ||c_k||^2
__device__ int   g_idx[MROWS];
__device__ float g_proto[20 * NDIM];

// ---- helpers ----------------------------------------------------------------
__device__ __forceinline__ uint32_t smem_u32(const void* p) {
    uint32_t a;
    asm("{ .reg .u64 t; cvta.to.shared.u64 t, %1; cvt.u32.u64 %0, t; }"
        : "=r"(a) : "l"(p));
    return a;
}
__device__ __forceinline__ void cp16(uint32_t dst, const void* src) {
    asm volatile("cp.async.cg.shared.global [%0], [%1], 16;"
                 :: "r"(dst), "l"(src) : "memory");
}
#define CP_COMMIT() asm volatile("cp.async.commit_group;" ::: "memory")
#define CP_WAIT2()  asm volatile("cp.async.wait_group 2;" ::: "memory")

__device__ __forceinline__ void ldsm4(uint32_t& r0, uint32_t& r1,
                                      uint32_t& r2, uint32_t& r3, uint32_t a) {
    asm volatile("ldmatrix.sync.aligned.m8n8.x4.shared.b16 {%0,%1,%2,%3}, [%4];"
                 : "=r"(r0), "=r"(r1), "=r"(r2), "=r"(r3) : "r"(a));
}
__device__ __forceinline__ void mma16816(float* c, const uint32_t* a,
                                         const uint32_t* b) {
    asm volatile(
        "mma.sync.aligned.m16n8k16.row.col.f32.bf16.bf16.f32 "
        "{%0,%1,%2,%3},{%4,%5,%6,%7},{%8,%9},{%0,%1,%2,%3};"
        : "+f"(c[0]), "+f"(c[1]), "+f"(c[2]), "+f"(c[3])
        : "r"(a[0]), "r"(a[1]), "r"(a[2]), "r"(a[3]), "r"(b[0]), "r"(b[1]));
}
__device__ __forceinline__ uint32_t toff(int r, int c) {
    return (uint32_t)(r * 64 + ((c ^ ((r >> 1) & 3)) << 4));
}

// ---- fast truncation split ---------------------------------------------------
__device__ __forceinline__ void split2(float f0, float f1,
                                       uint32_t& hp, uint32_t& lp) {
    const uint32_t u0 = __float_as_uint(f0);
    const uint32_t u1 = __float_as_uint(f1);
    asm("prmt.b32 %0, %1, %2, 0x7632;" : "=r"(hp) : "r"(u0), "r"(u1));
    const float lo0 = f0 - __uint_as_float(u0 & 0xFFFF0000u);
    const float lo1 = f1 - __uint_as_float(u1 & 0xFFFF0000u);
    asm("cvt.rn.bf16x2.f32 %0, %1, %2;" : "=r"(lp) : "f"(lo1), "f"(lo0));
}
__device__ __forceinline__ void split8(const float* f, uint4& hv, uint4& lv) {
    split2(f[0], f[1], hv.x, lv.x);
    split2(f[2], f[3], hv.y, lv.y);
    split2(f[4], f[5], hv.z, lv.z);
    split2(f[6], f[7], hv.w, lv.w);
}

// ---- block-wide sum over 512 threads (3 barriers, deterministic) ------------
__device__ __forceinline__ float blk_sum512(float v, float* s16, int t) {
    __syncthreads();                       // protect s16 reuse
    const int lane = t & 31, warp = t >> 5;
#pragma unroll
    for (int o = 16; o > 0; o >>= 1) v += __shfl_xor_sync(0xffffffffu, v, o);
    if (lane == 0) s16[warp] = v;
    __syncthreads();
    if (warp == 0) {
        float w = (lane < 16) ? s16[lane] : 0.f;
#pragma unroll
        for (int o = 8; o > 0; o >>= 1) w += __shfl_xor_sync(0xffffffffu, w, o);
        if (lane == 0) s16[0] = w;
    }
    __syncthreads();
    return s16[0];
}

// ============================================================================
// conv_all: A split | B transpose+split | cbT transpose
// ============================================================================
__global__ __launch_bounds__(256) void conv_all(const float* __restrict__ xs,
                                                const float* __restrict__ xq,
                                                const float* __restrict__ W,
                                                const float* __restrict__ cb) {
    __shared__ float ts[64][65];
    const int t = threadIdx.x;
    int bid = blockIdx.x;

    if (bid < A_BLOCKS) {
        const size_t e = ((size_t)bid * 256 + t) * 16;
        const int row = (int)(e / IN_DIM);
        const int col = (int)(e % IN_DIM);
        float f[16];
        const float* src = 0;
        if (row < NSHOT)      src = xs + (size_t)row * IN_DIM + col;
        else if (row < MROWS) src = xq + (size_t)(row - NSHOT) * IN_DIM + col;
        if (src) {
#pragma unroll
            for (int i = 0; i < 4; i++)
                *(float4*)&f[i * 4] = *(const float4*)(src + i * 4);
        } else {
#pragma unroll
            for (int i = 0; i < 16; i++) f[i] = 0.f;
        }
        uint4 hv0, lv0, hv1, lv1;
        split8(f,     hv0, lv0);
        split8(f + 8, hv1, lv1);
        *(uint4*)&gAhi[e]     = hv0;
        *(uint4*)&gAhi[e + 8] = hv1;
        *(uint4*)&gAlo[e]     = lv0;
        *(uint4*)&gAlo[e + 8] = lv1;
        return;
    }
    bid -= A_BLOCKS;

    if (bid < B_BLOCKS) {
        // ---- B transpose + split: 64x64 fp32 tile of enc_w
        const int k0 = (bid % B_KT) * 64;
        const int n0 = (bid / B_KT) * 64;
#pragma unroll
        for (int i = 0; i < 4; i++) {
            const int r = i * 16 + (t >> 4);
            const int c = (t & 15) * 4;
            const float4 v = *(const float4*)(W + (size_t)(k0 + r) * NDIM + n0 + c);
            ts[r][c] = v.x; ts[r][c+1] = v.y; ts[r][c+2] = v.z; ts[r][c+3] = v.w;
        }
        __syncthreads();
        const int n  = t >> 2;
        const int kc = (t & 3) * 16;
        float f[16];
#pragma unroll
        for (int j = 0; j < 16; j++) f[j] = ts[kc + j][n];
        uint4 hv0, lv0, hv1, lv1;
        split8(f,     hv0, lv0);
        split8(f + 8, hv1, lv1);
        const size_t o = (size_t)(n0 + n) * IN_DIM + k0 + kc;
        *(uint4*)&gBhi[o]     = hv0;
        *(uint4*)&gBhi[o + 8] = hv1;
        *(uint4*)&gBlo[o]     = lv0;
        *(uint4*)&gBlo[o + 8] = lv1;
        return;
    }
    bid -= B_BLOCKS;

    // ---- codebook transpose: cb[D][K] -> g_cbT[K][D], 64x64 fp32 tile
    const int d0 = (bid & 7) * 64;
    const int k0 = (bid >> 3) * 64;
#pragma unroll
    for (int i = 0; i < 4; i++) {
        const int r = i * 16 + (t >> 4);
        const int c = (t & 15) * 4;
        const float4 v = *(const float4*)(cb + (size_t)(d0 + r) * NK + k0 + c);
        ts[r][c] = v.x; ts[r][c+1] = v.y; ts[r][c+2] = v.z; ts[r][c+3] = v.w;
    }
    __syncthreads();
    const int k  = t >> 2;          // local k row 0..63
    const int dc = (t & 3) * 16;    // local d chunk
#pragma unroll
    for (int j = 0; j < 16; j += 4) {
        float4 o;
        o.x = ts[dc + j][k];     o.y = ts[dc + j + 1][k];
        o.z = ts[dc + j + 2][k]; o.w = ts[dc + j + 3][k];
        *(float4*)&g_cbT[(size_t)(k0 + k) * NDIM + d0 + dc + j] = o;
    }
}

// ============================================================================
// norms_kernel: 0.5*||c_k||^2 from g_cbT. 32 blocks x 512 thr, warp per code.
// ============================================================================
__global__ __launch_bounds__(512) void norms_kernel() {
    const int t = threadIdx.x;
    const int warp = t >> 5, lane = t & 31;
    const int k = blockIdx.x * 16 + warp;
    float s = 0.f;
#pragma unroll
    for (int i = 0; i < 16; i++) {
        const float c = g_cbT[(size_t)k * NDIM + lane + i * 32];
        s = fmaf(c, c, s);
    }
#pragma unroll
    for (int o = 16; o > 0; o >>= 1) s += __shfl_xor_sync(0xffffffffu, s, o);
    if (lane == 0) g_cnorm[k] = 0.5f * s;
}

// ============================================================================
// HMMA GEMM (R3/R7-proven): g_part[sp] = A_ph @ B_ph^T over k slice
// ============================================================================
__global__ __launch_bounds__(256, 2) void gemm_hmma() {
    extern __shared__ char smem[];
    const uint32_t sbase = smem_u32(smem);
    const int t = threadIdx.x;
    const int wid = t >> 5, lane = t & 31;

    const int n0 = blockIdx.x * BN;
    const int m0 = blockIdx.y * BM;
    const int sp = blockIdx.z;
    const int phase = sp / SUBSPLITS;
    const size_t ksub = (size_t)(sp % SUBSPLITS) * KSPLIT;

    const __nv_bfloat16* __restrict__ A = (phase == 2) ? gAlo : gAhi;
    const __nv_bfloat16* __restrict__ B = (phase == 1) ? gBlo : gBhi;

    const int lr = t >> 2;
    const int lc = t & 3;
    const uint32_t dA1 = toff(lr, lc),        dA2 = toff(lr + 64, lc);
    const uint32_t dB1 = toff(lr, lc) + 8192, dB2 = toff(lr + 64, lc) + 8192;
    const __nv_bfloat16* pA1 = A + (size_t)(m0 + lr) * IN_DIM + ksub + lc * 8;
    const __nv_bfloat16* pA2 = pA1 + (size_t)64 * IN_DIM;
    const __nv_bfloat16* pB1 = B + (size_t)(n0 + lr) * IN_DIM + ksub + lc * 8;
    const __nv_bfloat16* pB2 = pB1 + (size_t)64 * IN_DIM;

#define LOAD_STAGE(s, kt) do {                                        \
        const uint32_t sb_ = sbase + (s) * STG_BYTES;                  \
        const size_t ko_ = (size_t)(kt) * BK;                          \
        cp16(sb_ + dA1, pA1 + ko_); cp16(sb_ + dA2, pA2 + ko_);        \
        cp16(sb_ + dB1, pB1 + ko_); cp16(sb_ + dB2, pB2 + ko_);        \
    } while (0)

    const int wm = wid >> 1, wn = wid & 1;
    const int fr = lane & 15, fc = lane >> 4;
    uint32_t aoff[2][2], boff[4][2];
#pragma unroll
    for (int mh = 0; mh < 2; mh++)
#pragma unroll
        for (int ks = 0; ks < 2; ks++)
            aoff[mh][ks] = toff(wm * 32 + mh * 16 + fr, ks * 2 + fc);
#pragma unroll
    for (int p = 0; p < 4; p++)
#pragma unroll
        for (int ks = 0; ks < 2; ks++)
            boff[p][ks] = 8192 + toff(wn * 64 + p * 16 + fr, ks * 2 + fc);

    float c[2][8][4];
#pragma unroll
    for (int i = 0; i < 2; i++)
#pragma unroll
        for (int j = 0; j < 8; j++)
#pragma unroll
            for (int k = 0; k < 4; k++) c[i][j][k] = 0.f;

#pragma unroll
    for (int s = 0; s < STAGES - 1; s++) {
        LOAD_STAGE(s, s);
        CP_COMMIT();
    }

    for (int kt = 0; kt < NT; ++kt) {
        CP_WAIT2();
        __syncthreads();

        if (kt + STAGES - 1 < NT)
            LOAD_STAGE((kt + STAGES - 1) & (STAGES - 1), kt + STAGES - 1);
        CP_COMMIT();

        const uint32_t sb = sbase + (kt & (STAGES - 1)) * STG_BYTES;
#pragma unroll
        for (int ks = 0; ks < 2; ks++) {
            uint32_t a0[4], a1[4];
            ldsm4(a0[0], a0[1], a0[2], a0[3], sb + aoff[0][ks]);
            ldsm4(a1[0], a1[1], a1[2], a1[3], sb + aoff[1][ks]);
#pragma unroll
            for (int p = 0; p < 4; p++) {
                uint32_t r0, r1, r2, r3;
                ldsm4(r0, r1, r2, r3, sb + boff[p][ks]);
                uint32_t b0[2] = { r0, r2 };
                uint32_t b1[2] = { r1, r3 };
                mma16816(c[0][2*p],     a0, b0);
                mma16816(c[1][2*p],     a1, b0);
                mma16816(c[0][2*p + 1], a0, b1);
                mma16816(c[1][2*p + 1], a1, b1);
            }
        }
    }

    float* base = g_part + (size_t)sp * MPAD * NDIM;
    const int row0 = m0 + wm * 32 + (lane >> 2);
    const int col0 = n0 + wn * 64 + (lane & 3) * 2;
#pragma unroll
    for (int mi = 0; mi < 2; mi++)
#pragma unroll
        for (int j = 0; j < 8; j++) {
            const int r = row0 + mi * 16;
            const int cc = col0 + j * 8;
            *(float2*)&base[(size_t)r * NDIM + cc]       = make_float2(c[mi][j][0], c[mi][j][1]);
            *(float2*)&base[(size_t)(r + 8) * NDIM + cc] = make_float2(c[mi][j][2], c[mi][j][3]);
        }
}

// ============================================================================
// nearest_fused: split-K reduce + bias + nearest-codebook argmax.
// 400 blocks x 512 threads, 1 row each (occ ~2.7 CTA/SM). Deterministic.
// argmax_k ( z.c_k - 0.5||c_k||^2 ), tie -> min k.
// ============================================================================
__global__ __launch_bounds__(512) void nearest_fused(const float* __restrict__ bias,
                                                     const float* __restrict__ cb) {
    __shared__ float zs[NDIM];
    __shared__ float sv[16];
    __shared__ int   si[16];
    const int t = threadIdx.x;
    const int lane = t & 31, warp = t >> 5;
    const int row = blockIdx.x;

    // inline split-K reduction + bias (fixed order -> deterministic)
    {
        float s = 0.f;
#pragma unroll
        for (int p = 0; p < TOTSPLITS; p++)
            s += g_part[(size_t)p * MPAD * NDIM + (size_t)row * NDIM + t];
        zs[t] = s + bias[t];
    }
    __syncthreads();

    // dot product: thread t owns codebook column k = t (coalesced cb reads),
    // 4 independent accumulators for ILP.
    float a0 = 0.f, a1 = 0.f, a2 = 0.f, a3 = 0.f;
#pragma unroll 2
    for (int d = 0; d < NDIM; d += 4) {
        a0 = fmaf(zs[d + 0], cb[(size_t)(d + 0) * NK + t], a0);
        a1 = fmaf(zs[d + 1], cb[(size_t)(d + 1) * NK + t], a1);
        a2 = fmaf(zs[d + 2], cb[(size_t)(d + 2) * NK + t], a2);
        a3 = fmaf(zs[d + 3], cb[(size_t)(d + 3) * NK + t], a3);
    }
    float v = ((a0 + a1) + (a2 + a3)) - g_cnorm[t];
    int idx = t;

    // argmax (max value, tie -> min index)
#pragma unroll
    for (int o = 16; o > 0; o >>= 1) {
        const float ov = __shfl_down_sync(0xffffffffu, v, o);
        const int   oi = __shfl_down_sync(0xffffffffu, idx, o);
        if (ov > v || (ov == v && oi < idx)) { v = ov; idx = oi; }
    }
    if (lane == 0) { sv[warp] = v; si[warp] = idx; }
    __syncthreads();
    if (warp == 0) {
        float w = (lane < 16) ? sv[lane] : -3.4e38f;
        int   wi = (lane < 16) ? si[lane] : 0x7fffffff;
#pragma unroll
        for (int o = 8; o > 0; o >>= 1) {
            const float ov = __shfl_down_sync(0xffffffffu, w, o);
            const int   oi = __shfl_down_sync(0xffffffffu, wi, o);
            if (ov > w || (ov == w && oi < wi)) { w = ov; wi = oi; }
        }
        if (lane == 0) g_idx[row] = wi;
    }
}

// ============================================================================
// prototypes: mean of 5 quantized shots (coalesced cbT gathers), L2-normalized
// ============================================================================
__global__ __launch_bounds__(512) void proto_kernel() {
    __shared__ float s16[16];
    const int bw = blockIdx.x, t = threadIdx.x;
    float p = 0.f;
#pragma unroll
    for (int s = 0; s < 5; s++)
        p += g_cbT[(size_t)g_idx[bw * 5 + s] * NDIM + t];
    p *= 0.2f;
    const float nrm = blk_sum512(p * p, s16, t);
    g_proto[bw * NDIM + t] = p * rsqrtf(nrm);
}

// ============================================================================
// logits: coalesced cbT query gather, shfl block reductions
// ============================================================================
__global__ __launch_bounds__(512) void logits_kernel(
    const float* __restrict__ tptr, float* __restrict__ out) {
    __shared__ float s16[16];
    const int bq = blockIdx.x, t = threadIdx.x;
    const int b = bq / 75;
    const float v = g_cbT[(size_t)g_idx[NSHOT + bq] * NDIM + t];
    const float nrm = blk_sum512(v * v, s16, t);
    const float vn = v * rsqrtf(nrm);
    const float temp = *tptr;
#pragma unroll
    for (int w = 0; w < 5; w++) {
        const float d = blk_sum512(vn * g_proto[(b * 5 + w) * NDIM + t], s16, t);
        if (t == 0) out[bq * 5 + w] = d * temp;
    }
}

// ============================================================================
extern "C" void kernel_launch(void* const* d_in, const int* in_sizes, int n_in,
                              void* d_out, int out_size) {
    const float* xs   = (const float*)d_in[0];
    const float* xq   = (const float*)d_in[1];
    const float* W    = (const float*)d_in[2];
    const float* bias = (const float*)d_in[3];
    const float* cb   = (const float*)d_in[4];
    const float* temp = (const float*)d_in[5];
    float* out = (float*)d_out;

    cudaFuncSetAttribute(gemm_hmma, cudaFuncAttributeMaxDynamicSharedMemorySize,
                         SMEM_GEMM);

    conv_all<<<CONV_GRID, 256>>>(xs, xq, W, cb);
    norms_kernel<<<NK / 16, 512>>>();
    gemm_hmma<<<dim3(NDIM / BN, MPAD / BM, TOTSPLITS), 256, SMEM_GEMM>>>();
    nearest_fused<<<MROWS, 512>>>(bias, cb);   // launch #4: ncu target
    proto_kernel<<<20, 512>>>();
    logits_kernel<<<300, 512>>>(temp, out);
}

// round 12
// speedup vs baseline: 1.4079x; 1.0380x over previous
#include <cuda_runtime.h>
#include <cuda_bf16.h>
#include <cstdint>

// ============================================================================
// VQMetaBaseline via mma.sync bf16 (compute_103-safe):
// z_e = X @ W + b with truncation-based bf16 hi/lo split, 3 exact-product
// passes (hi*hi + hi*lo + lo*hi) as grid-z phases, fp32 accumulate ->
// argmin-index parity with fp32 reference. Tail: vectorized fused
// reduce+nearest (interleaved codebook), transposed-codebook proto/logits.
// ============================================================================

#define IN_DIM 49152
#define NDIM   512
#define NK     512
#define MROWS  400
#define MPAD   512
#define NSHOT  100

// GEMM tiling (R3/R7-proven config -- FROZEN)
#define BM 128
#define BN 128
#define BK 32
#define STAGES 4
#define STG_BYTES 16384            // A 8KB + B 8KB per stage
#define SMEM_GEMM (STAGES * STG_BYTES)   // 64 KB -> 2 CTAs/SM

// split-K: 3 phases (hihi, hilo, lohi) x 6 sub-splits
#define SUBSPLITS 6
#define TOTSPLITS 18
#define KSPLIT (IN_DIM / SUBSPLITS)      // 8192
#define NT (KSPLIT / BK)                 // 256 k-tiles per CTA

// conv_all work partition
#define A_BLOCKS ((int)((size_t)MPAD * IN_DIM / (256 * 16)))  // 6144
#define B_KT     (IN_DIM / 64)                                // 768
#define B_BLOCKS (B_KT * (NDIM / 64))                         // 6144
#define CBT_BLOCKS 64                                         // 8x8 64x64 tiles
#define CBI_BLOCKS 128                                        // d4-group repack
#define CONV_GRID (A_BLOCKS + B_BLOCKS + CBT_BLOCKS + CBI_BLOCKS)

// ---- scratch (static device globals; zero-initialized, no runtime alloc) ---
__device__ __align__(128) __nv_bfloat16 gAhi[(size_t)MPAD * IN_DIM];
__device__ __align__(128) __nv_bfloat16 gAlo[(size_t)MPAD * IN_DIM];
__device__ __align__(128) __nv_bfloat16 gBhi[(size_t)NDIM * IN_DIM];
__device__ __align__(128) __nv_bfloat16 gBlo[(size_t)NDIM * IN_DIM];
__device__ float g_part[(size_t)TOTSPLITS * MPAD * NDIM];
__device__ float g_cbT[NK * NDIM];      // codebook transposed [K][D]
__device__ __align__(16) float g_cbI[NDIM / 4 * NK * 4]; // [d/4][k][4] interleave
__device__ float g_cnorm[NK];           // 0.5 * ||c_k||^2
__device__ int   g_idx[MROWS];
__device__ float g_proto[20 * NDIM];

// ---- helpers ----------------------------------------------------------------
__device__ __forceinline__ uint32_t smem_u32(const void* p) {
    uint32_t a;
    asm("{ .reg .u64 t; cvta.to.shared.u64 t, %1; cvt.u32.u64 %0, t; }"
        : "=r"(a) : "l"(p));
    return a;
}
__device__ __forceinline__ void cp16(uint32_t dst, const void* src) {
    asm volatile("cp.async.cg.shared.global [%0], [%1], 16;"
                 :: "r"(dst), "l"(src) : "memory");
}
#define CP_COMMIT() asm volatile("cp.async.commit_group;" ::: "memory")
#define CP_WAIT2()  asm volatile("cp.async.wait_group 2;" ::: "memory")

__device__ __forceinline__ void ldsm4(uint32_t& r0, uint32_t& r1,
                                      uint32_t& r2, uint32_t& r3, uint32_t a) {
    asm volatile("ldmatrix.sync.aligned.m8n8.x4.shared.b16 {%0,%1,%2,%3}, [%4];"
                 : "=r"(r0), "=r"(r1), "=r"(r2), "=r"(r3) : "r"(a));
}
__device__ __forceinline__ void mma16816(float* c, const uint32_t* a,
                                         const uint32_t* b) {
    asm volatile(
        "mma.sync.aligned.m16n8k16.row.col.f32.bf16.bf16.f32 "
        "{%0,%1,%2,%3},{%4,%5,%6,%7},{%8,%9},{%0,%1,%2,%3};"
        : "+f"(c[0]), "+f"(c[1]), "+f"(c[2]), "+f"(c[3])
        : "r"(a[0]), "r"(a[1]), "r"(a[2]), "r"(a[3]), "r"(b[0]), "r"(b[1]));
}
__device__ __forceinline__ uint32_t toff(int r, int c) {
    return (uint32_t)(r * 64 + ((c ^ ((r >> 1) & 3)) << 4));
}

// ---- fast truncation split ---------------------------------------------------
__device__ __forceinline__ void split2(float f0, float f1,
                                       uint32_t& hp, uint32_t& lp) {
    const uint32_t u0 = __float_as_uint(f0);
    const uint32_t u1 = __float_as_uint(f1);
    asm("prmt.b32 %0, %1, %2, 0x7632;" : "=r"(hp) : "r"(u0), "r"(u1));
    const float lo0 = f0 - __uint_as_float(u0 & 0xFFFF0000u);
    const float lo1 = f1 - __uint_as_float(u1 & 0xFFFF0000u);
    asm("cvt.rn.bf16x2.f32 %0, %1, %2;" : "=r"(lp) : "f"(lo1), "f"(lo0));
}
__device__ __forceinline__ void split8(const float* f, uint4& hv, uint4& lv) {
    split2(f[0], f[1], hv.x, lv.x);
    split2(f[2], f[3], hv.y, lv.y);
    split2(f[4], f[5], hv.z, lv.z);
    split2(f[6], f[7], hv.w, lv.w);
}

// ---- block-wide sum over 512 threads (3 barriers, deterministic) ------------
__device__ __forceinline__ float blk_sum512(float v, float* s16, int t) {
    __syncthreads();
    const int lane = t & 31, warp = t >> 5;
#pragma unroll
    for (int o = 16; o > 0; o >>= 1) v += __shfl_xor_sync(0xffffffffu, v, o);
    if (lane == 0) s16[warp] = v;
    __syncthreads();
    if (warp == 0) {
        float w = (lane < 16) ? s16[lane] : 0.f;
#pragma unroll
        for (int o = 8; o > 0; o >>= 1) w += __shfl_xor_sync(0xffffffffu, w, o);
        if (lane == 0) s16[0] = w;
    }
    __syncthreads();
    return s16[0];
}

// ============================================================================
// conv_all: A split | B transpose+split | cbT transpose | cbI interleave
// ============================================================================
__global__ __launch_bounds__(256) void conv_all(const float* __restrict__ xs,
                                                const float* __restrict__ xq,
                                                const float* __restrict__ W,
                                                const float* __restrict__ cb) {
    __shared__ float ts[64][65];
    const int t = threadIdx.x;
    int bid = blockIdx.x;

    if (bid < A_BLOCKS) {
        const size_t e = ((size_t)bid * 256 + t) * 16;
        const int row = (int)(e / IN_DIM);
        const int col = (int)(e % IN_DIM);
        const float* src = 0;
        if (row < NSHOT)      src = xs + (size_t)row * IN_DIM + col;
        else if (row < MROWS) src = xq + (size_t)(row - NSHOT) * IN_DIM + col;
        if (!src) return;   // pad rows 400..511 stay zero (zero-init globals)
        float f[16];
#pragma unroll
        for (int i = 0; i < 4; i++)
            *(float4*)&f[i * 4] = *(const float4*)(src + i * 4);
        uint4 hv0, lv0, hv1, lv1;
        split8(f,     hv0, lv0);
        split8(f + 8, hv1, lv1);
        *(uint4*)&gAhi[e]     = hv0;
        *(uint4*)&gAhi[e + 8] = hv1;
        *(uint4*)&gAlo[e]     = lv0;
        *(uint4*)&gAlo[e + 8] = lv1;
        return;
    }
    bid -= A_BLOCKS;

    if (bid < B_BLOCKS) {
        // ---- B transpose + split: 64x64 fp32 tile of enc_w
        const int k0 = (bid % B_KT) * 64;
        const int n0 = (bid / B_KT) * 64;
#pragma unroll
        for (int i = 0; i < 4; i++) {
            const int r = i * 16 + (t >> 4);
            const int c = (t & 15) * 4;
            const float4 v = *(const float4*)(W + (size_t)(k0 + r) * NDIM + n0 + c);
            ts[r][c] = v.x; ts[r][c+1] = v.y; ts[r][c+2] = v.z; ts[r][c+3] = v.w;
        }
        __syncthreads();
        const int n  = t >> 2;
        const int kc = (t & 3) * 16;
        float f[16];
#pragma unroll
        for (int j = 0; j < 16; j++) f[j] = ts[kc + j][n];
        uint4 hv0, lv0, hv1, lv1;
        split8(f,     hv0, lv0);
        split8(f + 8, hv1, lv1);
        const size_t o = (size_t)(n0 + n) * IN_DIM + k0 + kc;
        *(uint4*)&gBhi[o]     = hv0;
        *(uint4*)&gBhi[o + 8] = hv1;
        *(uint4*)&gBlo[o]     = lv0;
        *(uint4*)&gBlo[o + 8] = lv1;
        return;
    }
    bid -= B_BLOCKS;

    if (bid < CBT_BLOCKS) {
        // ---- codebook transpose: cb[D][K] -> g_cbT[K][D], 64x64 fp32 tile
        const int d0 = (bid & 7) * 64;
        const int k0 = (bid >> 3) * 64;
#pragma unroll
        for (int i = 0; i < 4; i++) {
            const int r = i * 16 + (t >> 4);
            const int c = (t & 15) * 4;
            const float4 v = *(const float4*)(cb + (size_t)(d0 + r) * NK + k0 + c);
            ts[r][c] = v.x; ts[r][c+1] = v.y; ts[r][c+2] = v.z; ts[r][c+3] = v.w;
        }
        __syncthreads();
        const int k  = t >> 2;
        const int dc = (t & 3) * 16;
#pragma unroll
        for (int j = 0; j < 16; j += 4) {
            float4 o;
            o.x = ts[dc + j][k];     o.y = ts[dc + j + 1][k];
            o.z = ts[dc + j + 2][k]; o.w = ts[dc + j + 3][k];
            *(float4*)&g_cbT[(size_t)(k0 + k) * NDIM + d0 + dc + j] = o;
        }
        return;
    }
    bid -= CBT_BLOCKS;

    // ---- cbI interleave: cbI[d4][k][j] = cb[4*d4+j][k]; block = d4, thr = 2 ks
    {
        const int d4 = bid;               // 0..127
        const int d = d4 * 4;
#pragma unroll
        for (int h = 0; h < 2; h++) {
            const int k = t + h * 256;
            float4 o;
            o.x = cb[(size_t)(d + 0) * NK + k];
            o.y = cb[(size_t)(d + 1) * NK + k];
            o.z = cb[(size_t)(d + 2) * NK + k];
            o.w = cb[(size_t)(d + 3) * NK + k];
            *(float4*)&g_cbI[((size_t)d4 * NK + k) * 4] = o;
        }
    }
}

// ============================================================================
// norms_kernel: 0.5*||c_k||^2 from g_cbT. 32 blocks x 512 thr, warp per code.
// ============================================================================
__global__ __launch_bounds__(512) void norms_kernel() {
    const int t = threadIdx.x;
    const int warp = t >> 5, lane = t & 31;
    const int k = blockIdx.x * 16 + warp;
    float s = 0.f;
#pragma unroll
    for (int i = 0; i < 16; i++) {
        const float c = g_cbT[(size_t)k * NDIM + lane + i * 32];
        s = fmaf(c, c, s);
    }
#pragma unroll
    for (int o = 16; o > 0; o >>= 1) s += __shfl_xor_sync(0xffffffffu, s, o);
    if (lane == 0) g_cnorm[k] = 0.5f * s;
}

// ============================================================================
// HMMA GEMM (R3/R7-proven, FROZEN): g_part[sp] = A_ph @ B_ph^T over k slice
// ============================================================================
__global__ __launch_bounds__(256, 2) void gemm_hmma() {
    extern __shared__ char smem[];
    const uint32_t sbase = smem_u32(smem);
    const int t = threadIdx.x;
    const int wid = t >> 5, lane = t & 31;

    const int n0 = blockIdx.x * BN;
    const int m0 = blockIdx.y * BM;
    const int sp = blockIdx.z;
    const int phase = sp / SUBSPLITS;
    const size_t ksub = (size_t)(sp % SUBSPLITS) * KSPLIT;

    const __nv_bfloat16* __restrict__ A = (phase == 2) ? gAlo : gAhi;
    const __nv_bfloat16* __restrict__ B = (phase == 1) ? gBlo : gBhi;

    const int lr = t >> 2;
    const int lc = t & 3;
    const uint32_t dA1 = toff(lr, lc),        dA2 = toff(lr + 64, lc);
    const uint32_t dB1 = toff(lr, lc) + 8192, dB2 = toff(lr + 64, lc) + 8192;
    const __nv_bfloat16* pA1 = A + (size_t)(m0 + lr) * IN_DIM + ksub + lc * 8;
    const __nv_bfloat16* pA2 = pA1 + (size_t)64 * IN_DIM;
    const __nv_bfloat16* pB1 = B + (size_t)(n0 + lr) * IN_DIM + ksub + lc * 8;
    const __nv_bfloat16* pB2 = pB1 + (size_t)64 * IN_DIM;

#define LOAD_STAGE(s, kt) do {                                        \
        const uint32_t sb_ = sbase + (s) * STG_BYTES;                  \
        const size_t ko_ = (size_t)(kt) * BK;                          \
        cp16(sb_ + dA1, pA1 + ko_); cp16(sb_ + dA2, pA2 + ko_);        \
        cp16(sb_ + dB1, pB1 + ko_); cp16(sb_ + dB2, pB2 + ko_);        \
    } while (0)

    const int wm = wid >> 1, wn = wid & 1;
    const int fr = lane & 15, fc = lane >> 4;
    uint32_t aoff[2][2], boff[4][2];
#pragma unroll
    for (int mh = 0; mh < 2; mh++)
#pragma unroll
        for (int ks = 0; ks < 2; ks++)
            aoff[mh][ks] = toff(wm * 32 + mh * 16 + fr, ks * 2 + fc);
#pragma unroll
    for (int p = 0; p < 4; p++)
#pragma unroll
        for (int ks = 0; ks < 2; ks++)
            boff[p][ks] = 8192 + toff(wn * 64 + p * 16 + fr, ks * 2 + fc);

    float c[2][8][4];
#pragma unroll
    for (int i = 0; i < 2; i++)
#pragma unroll
        for (int j = 0; j < 8; j++)
#pragma unroll
            for (int k = 0; k < 4; k++) c[i][j][k] = 0.f;

#pragma unroll
    for (int s = 0; s < STAGES - 1; s++) {
        LOAD_STAGE(s, s);
        CP_COMMIT();
    }

    for (int kt = 0; kt < NT; ++kt) {
        CP_WAIT2();
        __syncthreads();

        if (kt + STAGES - 1 < NT)
            LOAD_STAGE((kt + STAGES - 1) & (STAGES - 1), kt + STAGES - 1);
        CP_COMMIT();

        const uint32_t sb = sbase + (kt & (STAGES - 1)) * STG_BYTES;
#pragma unroll
        for (int ks = 0; ks < 2; ks++) {
            uint32_t a0[4], a1[4];
            ldsm4(a0[0], a0[1], a0[2], a0[3], sb + aoff[0][ks]);
            ldsm4(a1[0], a1[1], a1[2], a1[3], sb + aoff[1][ks]);
#pragma unroll
            for (int p = 0; p < 4; p++) {
                uint32_t r0, r1, r2, r3;
                ldsm4(r0, r1, r2, r3, sb + boff[p][ks]);
                uint32_t b0[2] = { r0, r2 };
                uint32_t b1[2] = { r1, r3 };
                mma16816(c[0][2*p],     a0, b0);
                mma16816(c[1][2*p],     a1, b0);
                mma16816(c[0][2*p + 1], a0, b1);
                mma16816(c[1][2*p + 1], a1, b1);
            }
        }
    }

    float* base = g_part + (size_t)sp * MPAD * NDIM;
    const int row0 = m0 + wm * 32 + (lane >> 2);
    const int col0 = n0 + wn * 64 + (lane & 3) * 2;
#pragma unroll
    for (int mi = 0; mi < 2; mi++)
#pragma unroll
        for (int j = 0; j < 8; j++) {
            const int r = row0 + mi * 16;
            const int cc = col0 + j * 8;
            *(float2*)&base[(size_t)r * NDIM + cc]       = make_float2(c[mi][j][0], c[mi][j][1]);
            *(float2*)&base[(size_t)(r + 8) * NDIM + cc] = make_float2(c[mi][j][2], c[mi][j][3]);
        }
}

// ============================================================================
// nearest_fused: split-K reduce + bias + nearest-codebook argmax.
// 400 blocks x 512 threads, 1 row each. Vectorized: LDS.128 z broadcast +
// coalesced LDG.128 interleaved codebook. Deterministic (same FMA order).
// ============================================================================
__global__ __launch_bounds__(512) void nearest_fused(const float* __restrict__ bias) {
    __shared__ __align__(16) float zs[NDIM];
    __shared__ float sv[16];
    __shared__ int   si[16];
    const int t = threadIdx.x;
    const int lane = t & 31, warp = t >> 5;
    const int row = blockIdx.x;

    // inline split-K reduction + bias (fixed order -> deterministic)
    {
        float s = 0.f;
#pragma unroll
        for (int p = 0; p < TOTSPLITS; p++)
            s += g_part[(size_t)p * MPAD * NDIM + (size_t)row * NDIM + t];
        zs[t] = s + bias[t];
    }
    __syncthreads();

    // dot product: thread t owns code k = t; cbI rows coalesced float4.
    float a0 = 0.f, a1 = 0.f, a2 = 0.f, a3 = 0.f;
#pragma unroll 4
    for (int d4 = 0; d4 < NDIM / 4; d4++) {
        const float4 z = *(const float4*)&zs[d4 * 4];
        const float4 c = *(const float4*)&g_cbI[((size_t)d4 * NK + t) * 4];
        a0 = fmaf(z.x, c.x, a0);
        a1 = fmaf(z.y, c.y, a1);
        a2 = fmaf(z.z, c.z, a2);
        a3 = fmaf(z.w, c.w, a3);
    }
    float v = ((a0 + a1) + (a2 + a3)) - g_cnorm[t];
    int idx = t;

    // argmax (max value, tie -> min index)
#pragma unroll
    for (int o = 16; o > 0; o >>= 1) {
        const float ov = __shfl_down_sync(0xffffffffu, v, o);
        const int   oi = __shfl_down_sync(0xffffffffu, idx, o);
        if (ov > v || (ov == v && oi < idx)) { v = ov; idx = oi; }
    }
    if (lane == 0) { sv[warp] = v; si[warp] = idx; }
    __syncthreads();
    if (warp == 0) {
        float w = (lane < 16) ? sv[lane] : -3.4e38f;
        int   wi = (lane < 16) ? si[lane] : 0x7fffffff;
#pragma unroll
        for (int o = 8; o > 0; o >>= 1) {
            const float ov = __shfl_down_sync(0xffffffffu, w, o);
            const int   oi = __shfl_down_sync(0xffffffffu, wi, o);
            if (ov > w || (ov == w && oi < wi)) { w = ov; wi = oi; }
        }
        if (lane == 0) g_idx[row] = wi;
    }
}

// ============================================================================
// prototypes: mean of 5 quantized shots (coalesced cbT gathers), L2-normalized
// ============================================================================
__global__ __launch_bounds__(512) void proto_kernel() {
    __shared__ float s16[16];
    const int bw = blockIdx.x, t = threadIdx.x;
    float p = 0.f;
#pragma unroll
    for (int s = 0; s < 5; s++)
        p += g_cbT[(size_t)g_idx[bw * 5 + s] * NDIM + t];
    p *= 0.2f;
    const float nrm = blk_sum512(p * p, s16, t);
    g_proto[bw * NDIM + t] = p * rsqrtf(nrm);
}

// ============================================================================
// logits: coalesced cbT query gather, shfl block reductions
// ============================================================================
__global__ __launch_bounds__(512) void logits_kernel(
    const float* __restrict__ tptr, float* __restrict__ out) {
    __shared__ float s16[16];
    const int bq = blockIdx.x, t = threadIdx.x;
    const int b = bq / 75;
    const float v = g_cbT[(size_t)g_idx[NSHOT + bq] * NDIM + t];
    const float nrm = blk_sum512(v * v, s16, t);
    const float vn = v * rsqrtf(nrm);
    const float temp = *tptr;
#pragma unroll
    for (int w = 0; w < 5; w++) {
        const float d = blk_sum512(vn * g_proto[(b * 5 + w) * NDIM + t], s16, t);
        if (t == 0) out[bq * 5 + w] = d * temp;
    }
}

// ============================================================================
extern "C" void kernel_launch(void* const* d_in, const int* in_sizes, int n_in,
                              void* d_out, int out_size) {
    const float* xs   = (const float*)d_in[0];
    const float* xq   = (const float*)d_in[1];
    const float* W    = (const float*)d_in[2];
    const float* bias = (const float*)d_in[3];
    const float* cb   = (const float*)d_in[4];
    const float* temp = (const float*)d_in[5];
    float* out = (float*)d_out;

    cudaFuncSetAttribute(gemm_hmma, cudaFuncAttributeMaxDynamicSharedMemorySize,
                         SMEM_GEMM);

    conv_all<<<CONV_GRID, 256>>>(xs, xq, W, cb);
    norms_kernel<<<NK / 16, 512>>>();
    gemm_hmma<<<dim3(NDIM / BN, MPAD / BM, TOTSPLITS), 256, SMEM_GEMM>>>();
    nearest_fused<<<MROWS, 512>>>(bias);   // launch #4: ncu target
    proto_kernel<<<20, 512>>>();
    logits_kernel<<<300, 512>>>(temp, out);
}